// round 6
// baseline (speedup 1.0000x reference)
#include <cuda_runtime.h>
#include <cstdint>

#define NN      100000
#define DIM     256
#define NRELS   8
#define EPR     160000

#define TM 64
#define KB 32
#define APAD 4
#define BPAD 8

#define A_STRIDE (KB + APAD)      // 36 floats = 144B (16B aligned)
#define B_STRIDE (DIM + BPAD)     // 264 floats = 1056B (16B aligned)
#define SMEM_BYTES ((2 * KB * B_STRIDE + 2 * TM * A_STRIDE) * 4 + 2 * TM * 4)

// Scratch for normalized int32 indices (metadata may be int32 or int64 — detected at runtime)
__device__ int g_src32[NRELS * EPR];
__device__ int g_dst32[NRELS * EPR];
__device__ int g_idx_is_i32;

__device__ __forceinline__ unsigned f2tf(float v) {
    unsigned r;
    asm("cvt.rna.tf32.f32 %0, %1;" : "=r"(r) : "f"(v));
    return r;
}

__device__ __forceinline__ void mma_tf32(float c[4], const unsigned a[4], const unsigned b[2]) {
    asm volatile(
        "mma.sync.aligned.m16n8k8.row.col.f32.tf32.tf32.f32 "
        "{%0,%1,%2,%3}, {%4,%5,%6,%7}, {%8,%9}, {%0,%1,%2,%3};\n"
        : "+f"(c[0]), "+f"(c[1]), "+f"(c[2]), "+f"(c[3])
        : "r"(a[0]), "r"(a[1]), "r"(a[2]), "r"(a[3]), "r"(b[0]), "r"(b[1]));
}

__device__ __forceinline__ void red_v4(float* addr, float v0, float v1, float v2, float v3) {
    asm volatile("red.global.add.v4.f32 [%0], {%1, %2, %3, %4};"
                 :: "l"(addr), "f"(v0), "f"(v1), "f"(v2), "f"(v3) : "memory");
}

__device__ __forceinline__ void cp_async16(uint32_t smem_addr, const void* gptr) {
    asm volatile("cp.async.cg.shared.global [%0], [%1], 16;"
                 :: "r"(smem_addr), "l"(gptr) : "memory");
}
__device__ __forceinline__ void cp_commit() {
    asm volatile("cp.async.commit_group;" ::: "memory");
}
__device__ __forceinline__ void cp_wait1() {
    asm volatile("cp.async.wait_group 1;" ::: "memory");
}

// ---------------------------------------------------------------------------
// Index dtype detection
// ---------------------------------------------------------------------------
__global__ void detect_idx_kernel(const void* srcbuf) {
    const long long* p = (const long long*)srcbuf;
    int tid = threadIdx.x;
    int bad = 0;
    #pragma unroll
    for (int i = 0; i < 4; i++) {
        long long v = p[tid * 4 + i];
        if (v < 0 || v >= NN) bad = 1;
    }
    int any = __syncthreads_or(bad);
    if (tid == 0) g_idx_is_i32 = any;   // any out-of-range -> data is int32
}

__global__ void convert_idx_kernel(const void* srcbuf, const void* dstbuf) {
    long long i = (long long)blockIdx.x * blockDim.x + threadIdx.x;
    if (i >= (long long)NRELS * EPR) return;
    if (g_idx_is_i32) {
        g_src32[i] = ((const int*)srcbuf)[i];
        g_dst32[i] = ((const int*)dstbuf)[i];
    } else {
        g_src32[i] = (int)((const long long*)srcbuf)[i];
        g_dst32[i] = (int)((const long long*)dstbuf)[i];
    }
}

// ---------------------------------------------------------------------------
// Software-pipelined tiled tf32 GEMM with cp.async double-buffered smem.
// Raw fp32 staged in smem; tf32 conversion happens at fragment-load time
// (bit-identical rounding to stage-time conversion).
// GATHER=false: C[m,:] = X[m,:] @ W, direct store (self loop).
// GATHER=true:  per relation, C[e,:] = X[src[e],:] @ W_rel, red.v4 scatter.
// Block: 256 threads = 8 warps (2x4), tile M=64 x N=256, K chunks of 32.
// ---------------------------------------------------------------------------
template<bool GATHER, bool ATOMIC>
__global__ __launch_bounds__(256) void rgcn_gemm_kernel(const float* __restrict__ X,
                                                        const float* __restrict__ W,
                                                        float* __restrict__ out)
{
    extern __shared__ float dyn[];
    float* BsBase = dyn;                               // [2][KB][B_STRIDE]
    float* AsBase = dyn + 2 * KB * B_STRIDE;           // [2][TM][A_STRIDE]
    int*   sSrc   = (int*)(AsBase + 2 * TM * A_STRIDE);
    int*   sDst   = sSrc + TM;

    const int tid = threadIdx.x;
    const int rel = GATHER ? blockIdx.y : 0;
    const long long base = (long long)blockIdx.x * TM;

    const float* Wr = GATHER ? (W + (size_t)rel * DIM * DIM) : W;

    if (tid < TM) {
        if constexpr (GATHER) {
            long long off = (long long)rel * EPR + base + tid;
            sSrc[tid] = g_src32[off];
            sDst[tid] = g_dst32[off];
        } else {
            long long r = base + tid;
            sSrc[tid] = (r < NN) ? (int)r : 0;
            sDst[tid] = (r < NN) ? (int)r : -1;
        }
    }
    __syncthreads();

    const int warp = tid >> 5;
    const int lane = tid & 31;
    const int wm = warp >> 2;     // 0..1
    const int wn = warp & 3;      // 0..3
    const int g  = lane >> 2;     // 0..7
    const int t4 = lane & 3;      // 0..3

    const int arow  = tid >> 3;          // 0..31
    const int acol  = (tid & 7) << 2;    // 0,4,..,28
    const int brow0 = tid >> 6;          // 0..3
    const int bcol  = (tid & 63) << 2;   // 0,4,..,252

    // Fixed gather source rows for this thread's two A-stage rows
    const float* aPtr0 = X + (size_t)sSrc[arow]      * DIM + acol;
    const float* aPtr1 = X + (size_t)sSrc[arow + 32] * DIM + acol;
    const float* bPtr  = Wr + (size_t)brow0 * DIM + bcol;

    // smem byte addresses for this thread's staging slots
    const uint32_t sA0 = (uint32_t)__cvta_generic_to_shared(
        AsBase + (size_t)arow * A_STRIDE + acol);
    const uint32_t sA1 = (uint32_t)__cvta_generic_to_shared(
        AsBase + (size_t)(arow + 32) * A_STRIDE + acol);
    const uint32_t sB0 = (uint32_t)__cvta_generic_to_shared(
        BsBase + (size_t)brow0 * B_STRIDE + bcol);
    const uint32_t ABUF = (uint32_t)(TM * A_STRIDE * 4);   // byte stride between A buffers
    const uint32_t BBUF = (uint32_t)(KB * B_STRIDE * 4);   // byte stride between B buffers

    auto stage = [&](int kb, int buf) {
        uint32_t aoff = buf ? ABUF : 0u;
        uint32_t boff = buf ? BBUF : 0u;
        cp_async16(sA0 + aoff, aPtr0 + kb);
        cp_async16(sA1 + aoff, aPtr1 + kb);
        #pragma unroll
        for (int rr = 0; rr < 8; rr++)
            cp_async16(sB0 + boff + rr * 4 * B_STRIDE * 4,
                       bPtr + (size_t)(kb + rr * 4) * DIM);
    };

    float c[2][8][4];
    #pragma unroll
    for (int mi = 0; mi < 2; mi++)
        #pragma unroll
        for (int j = 0; j < 8; j++)
            #pragma unroll
            for (int q = 0; q < 4; q++)
                c[mi][j][q] = 0.f;

    // Prefetch chunk 0
    stage(0, 0);
    cp_commit();

    const int NCHUNK = DIM / KB;   // 8
    for (int kc = 0; kc < NCHUNK; kc++) {
        // Issue next chunk (always commit to keep group accounting uniform)
        if (kc + 1 < NCHUNK) stage((kc + 1) * KB, (kc + 1) & 1);
        cp_commit();
        cp_wait1();          // current chunk's group complete
        __syncthreads();

        const float* Ab = AsBase + (size_t)(kc & 1) * TM * A_STRIDE;
        const float* Bb = BsBase + (size_t)(kc & 1) * KB * B_STRIDE;

        #pragma unroll
        for (int s = 0; s < 4; s++) {
            unsigned a[2][4], b[8][2];
            #pragma unroll
            for (int mi = 0; mi < 2; mi++) {
                int rb = wm * 32 + mi * 16 + g;
                a[mi][0] = f2tf(Ab[(size_t)rb        * A_STRIDE + 8 * s + t4]);
                a[mi][1] = f2tf(Ab[(size_t)(rb + 8)  * A_STRIDE + 8 * s + t4]);
                a[mi][2] = f2tf(Ab[(size_t)rb        * A_STRIDE + 8 * s + t4 + 4]);
                a[mi][3] = f2tf(Ab[(size_t)(rb + 8)  * A_STRIDE + 8 * s + t4 + 4]);
            }
            #pragma unroll
            for (int j = 0; j < 8; j++) {
                int n = wn * 64 + j * 8 + g;
                b[j][0] = f2tf(Bb[(size_t)(8 * s + t4)     * B_STRIDE + n]);
                b[j][1] = f2tf(Bb[(size_t)(8 * s + t4 + 4) * B_STRIDE + n]);
            }
            #pragma unroll
            for (int mi = 0; mi < 2; mi++)
                #pragma unroll
                for (int j = 0; j < 8; j++)
                    mma_tf32(c[mi][j], a[mi], b[j]);
        }
        __syncthreads();   // WAR: all warps done with this buffer before next overwrite
    }

    // ---- epilogue ----
    if constexpr (ATOMIC) {
        const bool odd = (lane & 1);
        const int colbase = wn * 64 + ((t4 & ~1) << 1);   // 16B-aligned column
        #pragma unroll
        for (int mi = 0; mi < 2; mi++) {
            int rowsel = wm * 32 + mi * 16 + (odd ? 8 : 0) + g;
            int drow = sDst[rowsel];
            float* addr = out + (size_t)drow * DIM + colbase;
            #pragma unroll
            for (int j = 0; j < 8; j++) {
                float s0 = __shfl_xor_sync(0xffffffffu, odd ? c[mi][j][0] : c[mi][j][2], 1);
                float s1 = __shfl_xor_sync(0xffffffffu, odd ? c[mi][j][1] : c[mi][j][3], 1);
                float v0, v1, v2, v3;
                if (!odd) { v0 = c[mi][j][0]; v1 = c[mi][j][1]; v2 = s0; v3 = s1; }
                else      { v0 = s0;          v1 = s1;          v2 = c[mi][j][2]; v3 = c[mi][j][3]; }
                red_v4(addr + j * 8, v0, v1, v2, v3);
            }
        }
    } else {
        #pragma unroll
        for (int mi = 0; mi < 2; mi++) {
            #pragma unroll
            for (int half = 0; half < 2; half++) {
                int r = wm * 32 + mi * 16 + half * 8 + g;
                int drow = sDst[r];
                if (drow < 0) continue;
                float* orow = out + (size_t)drow * DIM + wn * 64;
                #pragma unroll
                for (int j = 0; j < 8; j++) {
                    int col = j * 8 + t4 * 2;
                    float v0 = c[mi][j][half * 2 + 0];
                    float v1 = c[mi][j][half * 2 + 1];
                    *reinterpret_cast<float2*>(orow + col) = make_float2(v0, v1);
                }
            }
        }
    }
}

// ---------------------------------------------------------------------------
// LayerNorm over last dim (256). One warp per row.
// ---------------------------------------------------------------------------
__global__ void ln_kernel(float* __restrict__ out,
                          const float* __restrict__ gamma,
                          const float* __restrict__ beta)
{
    int row = blockIdx.x * 8 + (threadIdx.x >> 5);
    if (row >= NN) return;
    int lane = threadIdx.x & 31;
    float* p = out + (size_t)row * DIM;

    float4 v0 = *reinterpret_cast<const float4*>(p + lane * 4);
    float4 v1 = *reinterpret_cast<const float4*>(p + 128 + lane * 4);

    float s  = v0.x + v0.y + v0.z + v0.w + v1.x + v1.y + v1.z + v1.w;
    float sq = fmaf(v0.x, v0.x, fmaf(v0.y, v0.y, fmaf(v0.z, v0.z, v0.w * v0.w)))
             + fmaf(v1.x, v1.x, fmaf(v1.y, v1.y, fmaf(v1.z, v1.z, v1.w * v1.w)));

    #pragma unroll
    for (int o = 16; o; o >>= 1) {
        s  += __shfl_xor_sync(0xffffffffu, s,  o);
        sq += __shfl_xor_sync(0xffffffffu, sq, o);
    }

    float mean = s * (1.f / 256.f);
    float var  = sq * (1.f / 256.f) - mean * mean;
    float rs   = rsqrtf(var + 1e-5f);

    float4 g0 = *reinterpret_cast<const float4*>(gamma + lane * 4);
    float4 g1 = *reinterpret_cast<const float4*>(gamma + 128 + lane * 4);
    float4 b0 = *reinterpret_cast<const float4*>(beta + lane * 4);
    float4 b1 = *reinterpret_cast<const float4*>(beta + 128 + lane * 4);

    v0.x = (v0.x - mean) * rs * g0.x + b0.x;
    v0.y = (v0.y - mean) * rs * g0.y + b0.y;
    v0.z = (v0.z - mean) * rs * g0.z + b0.z;
    v0.w = (v0.w - mean) * rs * g0.w + b0.w;
    v1.x = (v1.x - mean) * rs * g1.x + b1.x;
    v1.y = (v1.y - mean) * rs * g1.y + b1.y;
    v1.z = (v1.z - mean) * rs * g1.z + b1.z;
    v1.w = (v1.w - mean) * rs * g1.w + b1.w;

    *reinterpret_cast<float4*>(p + lane * 4)       = v0;
    *reinterpret_cast<float4*>(p + 128 + lane * 4) = v1;
}

extern "C" void kernel_launch(void* const* d_in, const int* in_sizes, int n_in,
                              void* d_out, int out_size)
{
    const float* x     = (const float*)d_in[0];
    const void*  srcb  = d_in[1];
    const void*  dstb  = d_in[2];
    const float* Wself = (const float*)d_in[3];
    const float* Wrel  = (const float*)d_in[4];
    const float* gamma = (const float*)d_in[5];
    const float* beta  = (const float*)d_in[6];
    float* out = (float*)d_out;

    // Allow >48KB dynamic smem (attribute set is idempotent & capture-safe)
    cudaFuncSetAttribute(rgcn_gemm_kernel<false, false>,
                         cudaFuncAttributeMaxDynamicSharedMemorySize, SMEM_BYTES);
    cudaFuncSetAttribute(rgcn_gemm_kernel<true, true>,
                         cudaFuncAttributeMaxDynamicSharedMemorySize, SMEM_BYTES);

    // Normalize indices to int32 scratch (handles int32 or int64 input dtype)
    detect_idx_kernel<<<1, 256>>>(srcb);
    {
        long long total = (long long)NRELS * EPR;
        int blocks = (int)((total + 255) / 256);
        convert_idx_kernel<<<blocks, 256>>>(srcb, dstb);
    }

    // 1) self loop: out = x @ W_self  (initializes all of out)
    rgcn_gemm_kernel<false, false><<<(NN + TM - 1) / TM, 256, SMEM_BYTES>>>(x, Wself, out);

    // 2) fused gather -> tf32 GEMM -> red.v4 scatter for all relations
    rgcn_gemm_kernel<true, true><<<dim3(EPR / TM, NRELS), 256, SMEM_BYTES>>>(x, Wrel, out);

    // 3) LayerNorm
    ln_kernel<<<(NN + 7) / 8, 256>>>(out, gamma, beta);
}

// round 7
// speedup vs baseline: 1.3038x; 1.3038x over previous
#include <cuda_runtime.h>
#include <cstdint>

#define NN      100000
#define DIM     256
#define NRELS   8
#define EPR     160000

#define TM 64
#define KB 32
#define APAD 4
#define BPAD 8

#define A_STRIDE (KB + APAD)      // 36 floats = 144B (16B aligned)
#define B_STRIDE (DIM + BPAD)     // 264 floats = 1056B (16B aligned)
#define SMEM_BYTES ((2 * KB * B_STRIDE + 2 * TM * A_STRIDE) * 4 + 2 * TM * 4)

// Scratch for normalized int32 indices (metadata may be int32 or int64 — detected at runtime)
__device__ int g_src32[NRELS * EPR];
__device__ int g_dst32[NRELS * EPR];
__device__ int g_idx_is_i32;

__device__ __forceinline__ void mma_tf32(float c[4], const unsigned a[4], const unsigned b[2]) {
    asm volatile(
        "mma.sync.aligned.m16n8k8.row.col.f32.tf32.tf32.f32 "
        "{%0,%1,%2,%3}, {%4,%5,%6,%7}, {%8,%9}, {%0,%1,%2,%3};\n"
        : "+f"(c[0]), "+f"(c[1]), "+f"(c[2]), "+f"(c[3])
        : "r"(a[0]), "r"(a[1]), "r"(a[2]), "r"(a[3]), "r"(b[0]), "r"(b[1]));
}

__device__ __forceinline__ void red_v4(float* addr, float v0, float v1, float v2, float v3) {
    asm volatile("red.global.add.v4.f32 [%0], {%1, %2, %3, %4};"
                 :: "l"(addr), "f"(v0), "f"(v1), "f"(v2), "f"(v3) : "memory");
}

__device__ __forceinline__ void cp_async16(uint32_t smem_addr, const void* gptr) {
    asm volatile("cp.async.cg.shared.global [%0], [%1], 16;"
                 :: "r"(smem_addr), "l"(gptr) : "memory");
}
__device__ __forceinline__ void cp_commit() {
    asm volatile("cp.async.commit_group;" ::: "memory");
}
__device__ __forceinline__ void cp_wait1() {
    asm volatile("cp.async.wait_group 1;" ::: "memory");
}

// ---------------------------------------------------------------------------
// Index dtype detection
// ---------------------------------------------------------------------------
__global__ void detect_idx_kernel(const void* srcbuf) {
    const long long* p = (const long long*)srcbuf;
    int tid = threadIdx.x;
    int bad = 0;
    #pragma unroll
    for (int i = 0; i < 4; i++) {
        long long v = p[tid * 4 + i];
        if (v < 0 || v >= NN) bad = 1;
    }
    int any = __syncthreads_or(bad);
    if (tid == 0) g_idx_is_i32 = any;   // any out-of-range -> data is int32
}

__global__ void convert_idx_kernel(const void* srcbuf, const void* dstbuf) {
    long long i = (long long)blockIdx.x * blockDim.x + threadIdx.x;
    if (i >= (long long)NRELS * EPR) return;
    if (g_idx_is_i32) {
        g_src32[i] = ((const int*)srcbuf)[i];
        g_dst32[i] = ((const int*)dstbuf)[i];
    } else {
        g_src32[i] = (int)((const long long*)srcbuf)[i];
        g_dst32[i] = (int)((const long long*)dstbuf)[i];
    }
}

// ---------------------------------------------------------------------------
// Software-pipelined tiled tf32 GEMM with cp.async double-buffered smem.
// Raw fp32 staged in smem and fed DIRECTLY to the tf32 MMA: the tensor core
// reads only the tf32 bit-fields of the 32-bit register, truncating the low
// 13 mantissa bits. No cvt instructions anywhere in the mainloop. LayerNorm's
// scale invariance cancels the systematic truncation shrink.
// GATHER=false: C[m,:] = X[m,:] @ W, direct store (self loop).
// GATHER=true:  per relation, C[e,:] = X[src[e],:] @ W_rel, red.v4 scatter.
// Block: 256 threads = 8 warps (2x4), tile M=64 x N=256, K chunks of 32.
// ---------------------------------------------------------------------------
template<bool GATHER, bool ATOMIC>
__global__ __launch_bounds__(256) void rgcn_gemm_kernel(const float* __restrict__ X,
                                                        const float* __restrict__ W,
                                                        float* __restrict__ out)
{
    extern __shared__ float dyn[];
    float* BsBase = dyn;                               // [2][KB][B_STRIDE]
    float* AsBase = dyn + 2 * KB * B_STRIDE;           // [2][TM][A_STRIDE]
    int*   sSrc   = (int*)(AsBase + 2 * TM * A_STRIDE);
    int*   sDst   = sSrc + TM;

    const int tid = threadIdx.x;
    const int rel = GATHER ? blockIdx.y : 0;
    const long long base = (long long)blockIdx.x * TM;

    const float* Wr = GATHER ? (W + (size_t)rel * DIM * DIM) : W;

    if (tid < TM) {
        if constexpr (GATHER) {
            long long off = (long long)rel * EPR + base + tid;
            sSrc[tid] = g_src32[off];
            sDst[tid] = g_dst32[off];
        } else {
            long long r = base + tid;
            sSrc[tid] = (r < NN) ? (int)r : 0;
            sDst[tid] = (r < NN) ? (int)r : -1;
        }
    }
    __syncthreads();

    const int warp = tid >> 5;
    const int lane = tid & 31;
    const int wm = warp >> 2;     // 0..1
    const int wn = warp & 3;      // 0..3
    const int g  = lane >> 2;     // 0..7
    const int t4 = lane & 3;      // 0..3

    const int arow  = tid >> 3;          // 0..31
    const int acol  = (tid & 7) << 2;    // 0,4,..,28
    const int brow0 = tid >> 6;          // 0..3
    const int bcol  = (tid & 63) << 2;   // 0,4,..,252

    // Fixed gather source rows for this thread's two A-stage rows
    const float* aPtr0 = X + (size_t)sSrc[arow]      * DIM + acol;
    const float* aPtr1 = X + (size_t)sSrc[arow + 32] * DIM + acol;
    const float* bPtr  = Wr + (size_t)brow0 * DIM + bcol;

    // smem byte addresses for this thread's staging slots
    const uint32_t sA0 = (uint32_t)__cvta_generic_to_shared(
        AsBase + (size_t)arow * A_STRIDE + acol);
    const uint32_t sA1 = (uint32_t)__cvta_generic_to_shared(
        AsBase + (size_t)(arow + 32) * A_STRIDE + acol);
    const uint32_t sB0 = (uint32_t)__cvta_generic_to_shared(
        BsBase + (size_t)brow0 * B_STRIDE + bcol);
    const uint32_t ABUF = (uint32_t)(TM * A_STRIDE * 4);   // byte stride between A buffers
    const uint32_t BBUF = (uint32_t)(KB * B_STRIDE * 4);   // byte stride between B buffers

    auto stage = [&](int kb, int buf) {
        uint32_t aoff = buf ? ABUF : 0u;
        uint32_t boff = buf ? BBUF : 0u;
        cp_async16(sA0 + aoff, aPtr0 + kb);
        cp_async16(sA1 + aoff, aPtr1 + kb);
        #pragma unroll
        for (int rr = 0; rr < 8; rr++)
            cp_async16(sB0 + boff + rr * 4 * B_STRIDE * 4,
                       bPtr + (size_t)(kb + rr * 4) * DIM);
    };

    float c[2][8][4];
    #pragma unroll
    for (int mi = 0; mi < 2; mi++)
        #pragma unroll
        for (int j = 0; j < 8; j++)
            #pragma unroll
            for (int q = 0; q < 4; q++)
                c[mi][j][q] = 0.f;

    // Prefetch chunk 0
    stage(0, 0);
    cp_commit();

    const int NCHUNK = DIM / KB;   // 8
    for (int kc = 0; kc < NCHUNK; kc++) {
        // Issue next chunk (always commit to keep group accounting uniform)
        if (kc + 1 < NCHUNK) stage((kc + 1) * KB, (kc + 1) & 1);
        cp_commit();
        cp_wait1();          // current chunk's group complete
        __syncthreads();

        const unsigned* Ab = (const unsigned*)(AsBase + (size_t)(kc & 1) * TM * A_STRIDE);
        const unsigned* Bb = (const unsigned*)(BsBase + (size_t)(kc & 1) * KB * B_STRIDE);

        #pragma unroll
        for (int s = 0; s < 4; s++) {
            unsigned a[2][4], b[8][2];
            #pragma unroll
            for (int mi = 0; mi < 2; mi++) {
                int rb = wm * 32 + mi * 16 + g;
                a[mi][0] = Ab[(size_t)rb        * A_STRIDE + 8 * s + t4];
                a[mi][1] = Ab[(size_t)(rb + 8)  * A_STRIDE + 8 * s + t4];
                a[mi][2] = Ab[(size_t)rb        * A_STRIDE + 8 * s + t4 + 4];
                a[mi][3] = Ab[(size_t)(rb + 8)  * A_STRIDE + 8 * s + t4 + 4];
            }
            #pragma unroll
            for (int j = 0; j < 8; j++) {
                int n = wn * 64 + j * 8 + g;
                b[j][0] = Bb[(size_t)(8 * s + t4)     * B_STRIDE + n];
                b[j][1] = Bb[(size_t)(8 * s + t4 + 4) * B_STRIDE + n];
            }
            #pragma unroll
            for (int mi = 0; mi < 2; mi++)
                #pragma unroll
                for (int j = 0; j < 8; j++)
                    mma_tf32(c[mi][j], a[mi], b[j]);
        }
        __syncthreads();   // WAR: all warps done with this buffer before next overwrite
    }

    // ---- epilogue ----
    if constexpr (ATOMIC) {
        const bool odd = (lane & 1);
        const int colbase = wn * 64 + ((t4 & ~1) << 1);   // 16B-aligned column
        #pragma unroll
        for (int mi = 0; mi < 2; mi++) {
            int rowsel = wm * 32 + mi * 16 + (odd ? 8 : 0) + g;
            int drow = sDst[rowsel];
            float* addr = out + (size_t)drow * DIM + colbase;
            #pragma unroll
            for (int j = 0; j < 8; j++) {
                float s0 = __shfl_xor_sync(0xffffffffu, odd ? c[mi][j][0] : c[mi][j][2], 1);
                float s1 = __shfl_xor_sync(0xffffffffu, odd ? c[mi][j][1] : c[mi][j][3], 1);
                float v0, v1, v2, v3;
                if (!odd) { v0 = c[mi][j][0]; v1 = c[mi][j][1]; v2 = s0; v3 = s1; }
                else      { v0 = s0;          v1 = s1;          v2 = c[mi][j][2]; v3 = c[mi][j][3]; }
                red_v4(addr + j * 8, v0, v1, v2, v3);
            }
        }
    } else {
        #pragma unroll
        for (int mi = 0; mi < 2; mi++) {
            #pragma unroll
            for (int half = 0; half < 2; half++) {
                int r = wm * 32 + mi * 16 + half * 8 + g;
                int drow = sDst[r];
                if (drow < 0) continue;
                float* orow = out + (size_t)drow * DIM + wn * 64;
                #pragma unroll
                for (int j = 0; j < 8; j++) {
                    int col = j * 8 + t4 * 2;
                    float v0 = c[mi][j][half * 2 + 0];
                    float v1 = c[mi][j][half * 2 + 1];
                    *reinterpret_cast<float2*>(orow + col) = make_float2(v0, v1);
                }
            }
        }
    }
}

// ---------------------------------------------------------------------------
// LayerNorm over last dim (256). One warp per row.
// ---------------------------------------------------------------------------
__global__ void ln_kernel(float* __restrict__ out,
                          const float* __restrict__ gamma,
                          const float* __restrict__ beta)
{
    int row = blockIdx.x * 8 + (threadIdx.x >> 5);
    if (row >= NN) return;
    int lane = threadIdx.x & 31;
    float* p = out + (size_t)row * DIM;

    float4 v0 = *reinterpret_cast<const float4*>(p + lane * 4);
    float4 v1 = *reinterpret_cast<const float4*>(p + 128 + lane * 4);

    float s  = v0.x + v0.y + v0.z + v0.w + v1.x + v1.y + v1.z + v1.w;
    float sq = fmaf(v0.x, v0.x, fmaf(v0.y, v0.y, fmaf(v0.z, v0.z, v0.w * v0.w)))
             + fmaf(v1.x, v1.x, fmaf(v1.y, v1.y, fmaf(v1.z, v1.z, v1.w * v1.w)));

    #pragma unroll
    for (int o = 16; o; o >>= 1) {
        s  += __shfl_xor_sync(0xffffffffu, s,  o);
        sq += __shfl_xor_sync(0xffffffffu, sq, o);
    }

    float mean = s * (1.f / 256.f);
    float var  = sq * (1.f / 256.f) - mean * mean;
    float rs   = rsqrtf(var + 1e-5f);

    float4 g0 = *reinterpret_cast<const float4*>(gamma + lane * 4);
    float4 g1 = *reinterpret_cast<const float4*>(gamma + 128 + lane * 4);
    float4 b0 = *reinterpret_cast<const float4*>(beta + lane * 4);
    float4 b1 = *reinterpret_cast<const float4*>(beta + 128 + lane * 4);

    v0.x = (v0.x - mean) * rs * g0.x + b0.x;
    v0.y = (v0.y - mean) * rs * g0.y + b0.y;
    v0.z = (v0.z - mean) * rs * g0.z + b0.z;
    v0.w = (v0.w - mean) * rs * g0.w + b0.w;
    v1.x = (v1.x - mean) * rs * g1.x + b1.x;
    v1.y = (v1.y - mean) * rs * g1.y + b1.y;
    v1.z = (v1.z - mean) * rs * g1.z + b1.z;
    v1.w = (v1.w - mean) * rs * g1.w + b1.w;

    *reinterpret_cast<float4*>(p + lane * 4)       = v0;
    *reinterpret_cast<float4*>(p + 128 + lane * 4) = v1;
}

extern "C" void kernel_launch(void* const* d_in, const int* in_sizes, int n_in,
                              void* d_out, int out_size)
{
    const float* x     = (const float*)d_in[0];
    const void*  srcb  = d_in[1];
    const void*  dstb  = d_in[2];
    const float* Wself = (const float*)d_in[3];
    const float* Wrel  = (const float*)d_in[4];
    const float* gamma = (const float*)d_in[5];
    const float* beta  = (const float*)d_in[6];
    float* out = (float*)d_out;

    // Allow >48KB dynamic smem (attribute set is idempotent & capture-safe)
    cudaFuncSetAttribute(rgcn_gemm_kernel<false, false>,
                         cudaFuncAttributeMaxDynamicSharedMemorySize, SMEM_BYTES);
    cudaFuncSetAttribute(rgcn_gemm_kernel<true, true>,
                         cudaFuncAttributeMaxDynamicSharedMemorySize, SMEM_BYTES);

    // Normalize indices to int32 scratch (handles int32 or int64 input dtype)
    detect_idx_kernel<<<1, 256>>>(srcb);
    {
        long long total = (long long)NRELS * EPR;
        int blocks = (int)((total + 255) / 256);
        convert_idx_kernel<<<blocks, 256>>>(srcb, dstb);
    }

    // 1) self loop: out = x @ W_self  (initializes all of out)
    rgcn_gemm_kernel<false, false><<<(NN + TM - 1) / TM, 256, SMEM_BYTES>>>(x, Wself, out);

    // 2) fused gather -> tf32 GEMM -> red.v4 scatter for all relations
    rgcn_gemm_kernel<true, true><<<dim3(EPR / TM, NRELS), 256, SMEM_BYTES>>>(x, Wrel, out);

    // 3) LayerNorm
    ln_kernel<<<(NN + 7) / 8, 256>>>(out, gamma, beta);
}

// round 8
// speedup vs baseline: 1.6276x; 1.2483x over previous
#include <cuda_runtime.h>
#include <cstdint>

#define NN      100000
#define DIM     256
#define NRELS   8
#define EPR     160000

#define TM 64
#define KB 32
#define APAD 4
#define BPAD 8

#define A_STRIDE (KB + APAD)      // 36 floats = 144B (16B aligned)
#define B_STRIDE (DIM + BPAD)     // 264 floats = 1056B (16B aligned)
#define SMEM_BYTES ((2 * KB * B_STRIDE + 2 * TM * A_STRIDE) * 4 + 2 * TM * 4)

// Scratch for normalized int32 indices (metadata may be int32 or int64 — detected at runtime)
__device__ int g_src32[NRELS * EPR];
__device__ int g_dst32[NRELS * EPR];
__device__ int g_idx_is_i32;

__device__ __forceinline__ void mma_tf32(float c[4], const unsigned a[4], const unsigned b[2]) {
    asm volatile(
        "mma.sync.aligned.m16n8k8.row.col.f32.tf32.tf32.f32 "
        "{%0,%1,%2,%3}, {%4,%5,%6,%7}, {%8,%9}, {%0,%1,%2,%3};\n"
        : "+f"(c[0]), "+f"(c[1]), "+f"(c[2]), "+f"(c[3])
        : "r"(a[0]), "r"(a[1]), "r"(a[2]), "r"(a[3]), "r"(b[0]), "r"(b[1]));
}

__device__ __forceinline__ void red_v4(float* addr, float v0, float v1, float v2, float v3) {
    asm volatile("red.global.add.v4.f32 [%0], {%1, %2, %3, %4};"
                 :: "l"(addr), "f"(v0), "f"(v1), "f"(v2), "f"(v3) : "memory");
}

__device__ __forceinline__ void cp_async16(uint32_t smem_addr, const void* gptr) {
    asm volatile("cp.async.cg.shared.global [%0], [%1], 16;"
                 :: "r"(smem_addr), "l"(gptr) : "memory");
}
__device__ __forceinline__ void cp_commit() {
    asm volatile("cp.async.commit_group;" ::: "memory");
}
__device__ __forceinline__ void cp_wait1() {
    asm volatile("cp.async.wait_group 1;" ::: "memory");
}

// ---------------------------------------------------------------------------
// Index dtype detection
// ---------------------------------------------------------------------------
__global__ void detect_idx_kernel(const void* srcbuf) {
    const long long* p = (const long long*)srcbuf;
    int tid = threadIdx.x;
    int bad = 0;
    #pragma unroll
    for (int i = 0; i < 4; i++) {
        long long v = p[tid * 4 + i];
        if (v < 0 || v >= NN) bad = 1;
    }
    int any = __syncthreads_or(bad);
    if (tid == 0) g_idx_is_i32 = any;   // any out-of-range -> data is int32
}

__global__ void convert_idx_kernel(const void* srcbuf, const void* dstbuf) {
    long long i = (long long)blockIdx.x * blockDim.x + threadIdx.x;
    if (i >= (long long)NRELS * EPR) return;
    if (g_idx_is_i32) {
        g_src32[i] = ((const int*)srcbuf)[i];
        g_dst32[i] = ((const int*)dstbuf)[i];
    } else {
        g_src32[i] = (int)((const long long*)srcbuf)[i];
        g_dst32[i] = (int)((const long long*)dstbuf)[i];
    }
}

// ---------------------------------------------------------------------------
// Software-pipelined tiled tf32 GEMM with cp.async double-buffered smem.
// Raw fp32 staged in smem and fed DIRECTLY to the tf32 MMA (truncation of the
// low 13 mantissa bits; LayerNorm's scale invariance cancels the systematic
// shrink). __launch_bounds__(256, 2) pins 2 blocks/SM (<=128 regs).
// GATHER=false: C[m,:] = X[m,:] @ W, direct store (self loop).
// GATHER=true:  per relation, C[e,:] = X[src[e],:] @ W_rel, red.v4 scatter.
// Block: 256 threads = 8 warps (2x4), tile M=64 x N=256, K chunks of 32.
// ---------------------------------------------------------------------------
template<bool GATHER, bool ATOMIC>
__global__ __launch_bounds__(256, 2) void rgcn_gemm_kernel(const float* __restrict__ X,
                                                           const float* __restrict__ W,
                                                           float* __restrict__ out)
{
    extern __shared__ float dyn[];
    float* BsBase = dyn;                               // [2][KB][B_STRIDE]
    float* AsBase = dyn + 2 * KB * B_STRIDE;           // [2][TM][A_STRIDE]
    int*   sSrc   = (int*)(AsBase + 2 * TM * A_STRIDE);
    int*   sDst   = sSrc + TM;

    const int tid = threadIdx.x;
    const int rel = GATHER ? blockIdx.y : 0;
    const long long base = (long long)blockIdx.x * TM;

    const float* Wr = GATHER ? (W + (size_t)rel * DIM * DIM) : W;

    if (tid < TM) {
        if constexpr (GATHER) {
            long long off = (long long)rel * EPR + base + tid;
            sSrc[tid] = g_src32[off];
            sDst[tid] = g_dst32[off];
        } else {
            long long r = base + tid;
            sSrc[tid] = (r < NN) ? (int)r : 0;
            sDst[tid] = (r < NN) ? (int)r : -1;
        }
    }
    __syncthreads();

    const int warp = tid >> 5;
    const int lane = tid & 31;
    const int wm = warp >> 2;     // 0..1
    const int wn = warp & 3;      // 0..3
    const int g  = lane >> 2;     // 0..7
    const int t4 = lane & 3;      // 0..3

    const int arow  = tid >> 3;          // 0..31
    const int acol  = (tid & 7) << 2;    // 0,4,..,28
    const int brow0 = tid >> 6;          // 0..3
    const int bcol  = (tid & 63) << 2;   // 0,4,..,252

    // Fixed gather source rows for this thread's two A-stage rows
    const float* aPtr0 = X + (size_t)sSrc[arow]      * DIM + acol;
    const float* aPtr1 = X + (size_t)sSrc[arow + 32] * DIM + acol;
    const float* bPtr  = Wr + (size_t)brow0 * DIM + bcol;

    // smem byte addresses for this thread's staging slots
    const uint32_t sA0 = (uint32_t)__cvta_generic_to_shared(
        AsBase + (size_t)arow * A_STRIDE + acol);
    const uint32_t sA1 = (uint32_t)__cvta_generic_to_shared(
        AsBase + (size_t)(arow + 32) * A_STRIDE + acol);
    const uint32_t sB0 = (uint32_t)__cvta_generic_to_shared(
        BsBase + (size_t)brow0 * B_STRIDE + bcol);
    const uint32_t ABUF = (uint32_t)(TM * A_STRIDE * 4);   // byte stride between A buffers
    const uint32_t BBUF = (uint32_t)(KB * B_STRIDE * 4);   // byte stride between B buffers

    auto stage = [&](int kb, int buf) {
        uint32_t aoff = buf ? ABUF : 0u;
        uint32_t boff = buf ? BBUF : 0u;
        cp_async16(sA0 + aoff, aPtr0 + kb);
        cp_async16(sA1 + aoff, aPtr1 + kb);
        #pragma unroll
        for (int rr = 0; rr < 8; rr++)
            cp_async16(sB0 + boff + rr * 4 * B_STRIDE * 4,
                       bPtr + (size_t)(kb + rr * 4) * DIM);
    };

    float c[2][8][4];
    #pragma unroll
    for (int mi = 0; mi < 2; mi++)
        #pragma unroll
        for (int j = 0; j < 8; j++)
            #pragma unroll
            for (int q = 0; q < 4; q++)
                c[mi][j][q] = 0.f;

    // Prefetch chunk 0
    stage(0, 0);
    cp_commit();

    const int NCHUNK = DIM / KB;   // 8
    for (int kc = 0; kc < NCHUNK; kc++) {
        // Issue next chunk (always commit to keep group accounting uniform)
        if (kc + 1 < NCHUNK) stage((kc + 1) * KB, (kc + 1) & 1);
        cp_commit();
        cp_wait1();          // current chunk's group complete
        __syncthreads();

        const unsigned* Ab = (const unsigned*)(AsBase + (size_t)(kc & 1) * TM * A_STRIDE);
        const unsigned* Bb = (const unsigned*)(BsBase + (size_t)(kc & 1) * KB * B_STRIDE);

        #pragma unroll
        for (int s = 0; s < 4; s++) {
            unsigned a[2][4], b[8][2];
            #pragma unroll
            for (int mi = 0; mi < 2; mi++) {
                int rb = wm * 32 + mi * 16 + g;
                a[mi][0] = Ab[(size_t)rb        * A_STRIDE + 8 * s + t4];
                a[mi][1] = Ab[(size_t)(rb + 8)  * A_STRIDE + 8 * s + t4];
                a[mi][2] = Ab[(size_t)rb        * A_STRIDE + 8 * s + t4 + 4];
                a[mi][3] = Ab[(size_t)(rb + 8)  * A_STRIDE + 8 * s + t4 + 4];
            }
            #pragma unroll
            for (int j = 0; j < 8; j++) {
                int n = wn * 64 + j * 8 + g;
                b[j][0] = Bb[(size_t)(8 * s + t4)     * B_STRIDE + n];
                b[j][1] = Bb[(size_t)(8 * s + t4 + 4) * B_STRIDE + n];
            }
            #pragma unroll
            for (int mi = 0; mi < 2; mi++)
                #pragma unroll
                for (int j = 0; j < 8; j++)
                    mma_tf32(c[mi][j], a[mi], b[j]);
        }
        __syncthreads();   // WAR: all warps done with this buffer before next overwrite
    }

    // ---- epilogue ----
    if constexpr (ATOMIC) {
        const bool odd = (lane & 1);
        const int colbase = wn * 64 + ((t4 & ~1) << 1);   // 16B-aligned column
        #pragma unroll
        for (int mi = 0; mi < 2; mi++) {
            int rowsel = wm * 32 + mi * 16 + (odd ? 8 : 0) + g;
            int drow = sDst[rowsel];
            float* addr = out + (size_t)drow * DIM + colbase;
            #pragma unroll
            for (int j = 0; j < 8; j++) {
                float s0 = __shfl_xor_sync(0xffffffffu, odd ? c[mi][j][0] : c[mi][j][2], 1);
                float s1 = __shfl_xor_sync(0xffffffffu, odd ? c[mi][j][1] : c[mi][j][3], 1);
                float v0, v1, v2, v3;
                if (!odd) { v0 = c[mi][j][0]; v1 = c[mi][j][1]; v2 = s0; v3 = s1; }
                else      { v0 = s0;          v1 = s1;          v2 = c[mi][j][2]; v3 = c[mi][j][3]; }
                red_v4(addr + j * 8, v0, v1, v2, v3);
            }
        }
    } else {
        #pragma unroll
        for (int mi = 0; mi < 2; mi++) {
            #pragma unroll
            for (int half = 0; half < 2; half++) {
                int r = wm * 32 + mi * 16 + half * 8 + g;
                int drow = sDst[r];
                if (drow < 0) continue;
                float* orow = out + (size_t)drow * DIM + wn * 64;
                #pragma unroll
                for (int j = 0; j < 8; j++) {
                    int col = j * 8 + t4 * 2;
                    float v0 = c[mi][j][half * 2 + 0];
                    float v1 = c[mi][j][half * 2 + 1];
                    *reinterpret_cast<float2*>(orow + col) = make_float2(v0, v1);
                }
            }
        }
    }
}

// ---------------------------------------------------------------------------
// LayerNorm over last dim (256). One warp per row.
// ---------------------------------------------------------------------------
__global__ void ln_kernel(float* __restrict__ out,
                          const float* __restrict__ gamma,
                          const float* __restrict__ beta)
{
    int row = blockIdx.x * 8 + (threadIdx.x >> 5);
    if (row >= NN) return;
    int lane = threadIdx.x & 31;
    float* p = out + (size_t)row * DIM;

    float4 v0 = *reinterpret_cast<const float4*>(p + lane * 4);
    float4 v1 = *reinterpret_cast<const float4*>(p + 128 + lane * 4);

    float s  = v0.x + v0.y + v0.z + v0.w + v1.x + v1.y + v1.z + v1.w;
    float sq = fmaf(v0.x, v0.x, fmaf(v0.y, v0.y, fmaf(v0.z, v0.z, v0.w * v0.w)))
             + fmaf(v1.x, v1.x, fmaf(v1.y, v1.y, fmaf(v1.z, v1.z, v1.w * v1.w)));

    #pragma unroll
    for (int o = 16; o; o >>= 1) {
        s  += __shfl_xor_sync(0xffffffffu, s,  o);
        sq += __shfl_xor_sync(0xffffffffu, sq, o);
    }

    float mean = s * (1.f / 256.f);
    float var  = sq * (1.f / 256.f) - mean * mean;
    float rs   = rsqrtf(var + 1e-5f);

    float4 g0 = *reinterpret_cast<const float4*>(gamma + lane * 4);
    float4 g1 = *reinterpret_cast<const float4*>(gamma + 128 + lane * 4);
    float4 b0 = *reinterpret_cast<const float4*>(beta + lane * 4);
    float4 b1 = *reinterpret_cast<const float4*>(beta + 128 + lane * 4);

    v0.x = (v0.x - mean) * rs * g0.x + b0.x;
    v0.y = (v0.y - mean) * rs * g0.y + b0.y;
    v0.z = (v0.z - mean) * rs * g0.z + b0.z;
    v0.w = (v0.w - mean) * rs * g0.w + b0.w;
    v1.x = (v1.x - mean) * rs * g1.x + b1.x;
    v1.y = (v1.y - mean) * rs * g1.y + b1.y;
    v1.z = (v1.z - mean) * rs * g1.z + b1.z;
    v1.w = (v1.w - mean) * rs * g1.w + b1.w;

    *reinterpret_cast<float4*>(p + lane * 4)       = v0;
    *reinterpret_cast<float4*>(p + 128 + lane * 4) = v1;
}

extern "C" void kernel_launch(void* const* d_in, const int* in_sizes, int n_in,
                              void* d_out, int out_size)
{
    const float* x     = (const float*)d_in[0];
    const void*  srcb  = d_in[1];
    const void*  dstb  = d_in[2];
    const float* Wself = (const float*)d_in[3];
    const float* Wrel  = (const float*)d_in[4];
    const float* gamma = (const float*)d_in[5];
    const float* beta  = (const float*)d_in[6];
    float* out = (float*)d_out;

    // Allow >48KB dynamic smem (attribute set is idempotent & capture-safe)
    cudaFuncSetAttribute(rgcn_gemm_kernel<false, false>,
                         cudaFuncAttributeMaxDynamicSharedMemorySize, SMEM_BYTES);
    cudaFuncSetAttribute(rgcn_gemm_kernel<true, true>,
                         cudaFuncAttributeMaxDynamicSharedMemorySize, SMEM_BYTES);

    // Normalize indices to int32 scratch (handles int32 or int64 input dtype)
    detect_idx_kernel<<<1, 256>>>(srcb);
    {
        long long total = (long long)NRELS * EPR;
        int blocks = (int)((total + 255) / 256);
        convert_idx_kernel<<<blocks, 256>>>(srcb, dstb);
    }

    // 1) self loop: out = x @ W_self  (initializes all of out)
    rgcn_gemm_kernel<false, false><<<(NN + TM - 1) / TM, 256, SMEM_BYTES>>>(x, Wself, out);

    // 2) fused gather -> tf32 GEMM -> red.v4 scatter for all relations
    rgcn_gemm_kernel<true, true><<<dim3(EPR / TM, NRELS), 256, SMEM_BYTES>>>(x, Wrel, out);

    // 3) LayerNorm
    ln_kernel<<<(NN + 7) / 8, 256>>>(out, gamma, beta);
}